// round 7
// baseline (speedup 1.0000x reference)
#include <cuda_runtime.h>
#include <math.h>

// Problem-fixed: N_TRAIN=131072, M_TEST=65536
#define TT     196608
#define LOGC   5
#define CHUNK  32
#define NCH    (TT / CHUNK)   // 6144
#define HALF   (NCH / 2)      // 3072 threads, 2 chains each
#define WARM   4096
#define STEPS  (WARM + CHUNK)

// Transposed merged inputs: index (j, chunk) -> j*NCH + chunk. (t, residual, R, is_obs)
__device__ float4 g_in_t[(size_t)CHUNK * NCH];
__device__ int    g_tj[TT];
// Filter record, SoA-transposed: field f of slot k at ((f*CHUNK + j)*NCH + c), c=k>>LOGC, j=k&(CHUNK-1)
//  F0=(mf0,mf1,mf2,mp0)  F1=(mp1,mp2,Pp00,Pp01)  F2=(Pp02,Pp11,Pp12,Pp22)
//  F3=(Pf00,Pf01,Pf02,Pf11)  F4=(Pf12,Pf22,G22,-)  F5=(G00,G01,G02,G10)  F6=(G11,G12,G20,G21)
// F4.xy written by slot owner; F4.z (G22) written by owner of slot+1. Disjoint 4B words.
__device__ float4 g_rec[(size_t)7 * CHUNK * NCH];

__device__ __forceinline__ size_t ridx(int f, int slot) {
    int c = slot >> LOGC, j = slot & (CHUNK - 1);
    return ((size_t)(f * CHUNK + j)) * NCH + c;
}
__device__ __forceinline__ size_t iidx(int k) {
    return (size_t)(k & (CHUNK - 1)) * NCH + (k >> LOGC);
}

__global__ void merge_kernel(const float* __restrict__ times, const float* __restrict__ tstar,
                             const float* __restrict__ n1, const float* __restrict__ n2,
                             const float* __restrict__ pmc, int N, int M) {
    int i = blockIdx.x * blockDim.x + threadIdx.x;
    if (i < N) {
        float x = times[i];
        // stable argsort: equal keys keep train first -> position = i + #{tstar < x}
        int lo = 0, hi = M;
        while (lo < hi) { int mid = (lo + hi) >> 1; if (tstar[mid] < x) lo = mid + 1; else hi = mid; }
        int p = i + lo;
        float s2 = n2[i];
        float mc = *pmc;
        g_in_t[iidx(p)] = make_float4(x, n1[i] / s2 - mc, 1.0f / s2, 1.0f);
        g_tj[p] = -1;
    } else if (i < N + M) {
        int j = i - N;
        float x = tstar[j];
        // position = j + #{times <= x}
        int lo = 0, hi = N;
        while (lo < hi) { int mid = (lo + hi) >> 1; if (times[mid] <= x) lo = mid + 1; else hi = mid; }
        int p = j + lo;
        g_in_t[iidx(p)] = make_float4(x, 0.0f, 1.0f, 0.0f);
        g_tj[p] = j;
    }
}

__global__ void __launch_bounds__(32) forward_kernel(const float* __restrict__ pvar,
                                                     const float* __restrict__ pls) {
    int t = blockIdx.x * blockDim.x + threadIdx.x;
    if (t >= HALF) return;
    const int s0 = t * CHUNK, s1 = (t + HALF) * CHUNK;
    const int s[2] = { s0, s1 };

    float var = *pvar;
    float lam = sqrtf(5.0f) / (*pls);
    float lam2 = lam * lam, lam3 = lam2 * lam, lam4 = lam2 * lam2;
    float kap = lam2 * (1.0f / 3.0f);
    float pi00 = var, pi02 = -var * kap, pi11 = var * kap, pi22 = var * lam4;

    float m0[2], m1[2], m2[2];
    float P00[2], P01[2], P02[2], P11[2], P12[2], P22[2];
    float tprev[2];
    float4 in[2];
#pragma unroll
    for (int u = 0; u < 2; u++) {
        m0[u] = m1[u] = m2[u] = 0.f;
        P00[u] = pi00; P01[u] = 0.f; P02[u] = pi02;
        P11[u] = pi11; P12[u] = 0.f; P22[u] = pi22;
        int k0 = s[u] - WARM;
        int kp = max(k0 - 1, 0);
        tprev[u] = g_in_t[iidx(kp)].x;          // unused until k>0 (dt forced 0 for k<=0)
        in[u] = g_in_t[iidx(max(k0, 0))];
    }

    for (int i = 0; i < STEPS; ++i) {
#pragma unroll
        for (int u = 0; u < 2; u++) {
            int k = s[u] - WARM + i;
            int kn = min(max(k + 1, 0), TT - 1);
            float4 nin = g_in_t[iidx(kn)];      // prefetch

            float dt = (k <= 0) ? 0.0f : (in[u].x - tprev[u]);
            tprev[u] = in[u].x;
            float r = in[u].y, R = in[u].z;
            float obs = (k < 0) ? 0.0f : in[u].w;  // k<0: identity step (dt=0, no update)

            float ed = __expf(-lam * dt);
            float d2 = 0.5f * dt * dt;
            float A00 = ed * (1.0f + dt * lam + d2 * lam2);
            float A01 = ed * (dt + d2 * (2.0f * lam));
            float A02 = ed * d2;
            float A10 = ed * (-d2 * lam3);
            float A11 = ed * (1.0f + dt * lam - d2 * (2.0f * lam2));
            float A12 = ed * (dt - d2 * lam);
            float A20 = ed * (-dt * lam3 + d2 * lam4);
            float A21 = ed * (-3.0f * dt * lam2 + d2 * (2.0f * lam3));
            float A22 = ed * (1.0f - 2.0f * dt * lam + d2 * lam2);

            // Delta = P - Pinf ; C = A*Delta ; P_pred = C A^T + Pinf
            float D00 = P00[u] - pi00, D01 = P01[u], D02 = P02[u] - pi02;
            float D11 = P11[u] - pi11, D12 = P12[u], D22 = P22[u] - pi22;
            float C00 = A00 * D00 + A01 * D01 + A02 * D02;
            float C01 = A00 * D01 + A01 * D11 + A02 * D12;
            float C02 = A00 * D02 + A01 * D12 + A02 * D22;
            float C10 = A10 * D00 + A11 * D01 + A12 * D02;
            float C11 = A10 * D01 + A11 * D11 + A12 * D12;
            float C12 = A10 * D02 + A11 * D12 + A12 * D22;
            float C20 = A20 * D00 + A21 * D01 + A22 * D02;
            float C21 = A20 * D01 + A21 * D11 + A22 * D12;
            float C22 = A20 * D02 + A21 * D12 + A22 * D22;
            float Pp00 = C00 * A00 + C01 * A01 + C02 * A02 + pi00;
            float Pp01 = C00 * A10 + C01 * A11 + C02 * A12;
            float Pp02 = C00 * A20 + C01 * A21 + C02 * A22 + pi02;
            float Pp11 = C10 * A10 + C11 * A11 + C12 * A12 + pi11;
            float Pp12 = C10 * A20 + C11 * A21 + C12 * A22;
            float Pp22 = C20 * A20 + C21 * A21 + C22 * A22 + pi22;

            float mp0 = A00 * m0[u] + A01 * m1[u] + A02 * m2[u];
            float mp1 = A10 * m0[u] + A11 * m1[u] + A12 * m2[u];
            float mp2 = A20 * m0[u] + A21 * m1[u] + A22 * m2[u];

            if (i >= WARM) {
                // Smoother gain for slot k-1: G = P_filt(k-1) A^T Ppred^{-1}
                if (k > 0) {
                    float AP00 = C00 + A00 * pi00 + A02 * pi02;
                    float AP01 = C01 + A01 * pi11;
                    float AP02 = C02 + A00 * pi02 + A02 * pi22;
                    float AP10 = C10 + A10 * pi00 + A12 * pi02;
                    float AP11 = C11 + A11 * pi11;
                    float AP12 = C12 + A10 * pi02 + A12 * pi22;
                    float AP20 = C20 + A20 * pi00 + A22 * pi02;
                    float AP21 = C21 + A21 * pi11;
                    float AP22 = C22 + A20 * pi02 + A22 * pi22;

                    float i00 = Pp11 * Pp22 - Pp12 * Pp12;
                    float i01 = Pp02 * Pp12 - Pp01 * Pp22;
                    float i02 = Pp01 * Pp12 - Pp02 * Pp11;
                    float i11 = Pp00 * Pp22 - Pp02 * Pp02;
                    float i12 = Pp01 * Pp02 - Pp00 * Pp12;
                    float i22 = Pp00 * Pp11 - Pp01 * Pp01;
                    float det = Pp00 * i00 + Pp01 * i01 + Pp02 * i02;
                    float idet = __fdividef(1.0f, det);
                    i00 *= idet; i01 *= idet; i02 *= idet;
                    i11 *= idet; i12 *= idet; i22 *= idet;

                    float G00 = AP00 * i00 + AP10 * i01 + AP20 * i02;
                    float G01 = AP00 * i01 + AP10 * i11 + AP20 * i12;
                    float G02 = AP00 * i02 + AP10 * i12 + AP20 * i22;
                    float G10 = AP01 * i00 + AP11 * i01 + AP21 * i02;
                    float G11 = AP01 * i01 + AP11 * i11 + AP21 * i12;
                    float G12 = AP01 * i02 + AP11 * i12 + AP21 * i22;
                    float G20 = AP02 * i00 + AP12 * i01 + AP22 * i02;
                    float G21 = AP02 * i01 + AP12 * i11 + AP22 * i12;
                    float G22 = AP02 * i02 + AP12 * i12 + AP22 * i22;

                    int q = k - 1;
                    g_rec[ridx(5, q)] = make_float4(G00, G01, G02, G10);
                    g_rec[ridx(6, q)] = make_float4(G11, G12, G20, G21);
                    ((float*)&g_rec[ridx(4, q)])[2] = G22;
                }
            }

            // Measurement update
            float S = Pp00 + R;
            float iS = __fdividef(obs, S);
            float K0 = Pp00 * iS, K1 = Pp01 * iS, K2 = Pp02 * iS;
            float v = r - mp0;
            m0[u] = mp0 + K0 * v; m1[u] = mp1 + K1 * v; m2[u] = mp2 + K2 * v;
            P00[u] = Pp00 - K0 * K0 * S;
            P01[u] = Pp01 - K0 * K1 * S;
            P02[u] = Pp02 - K0 * K2 * S;
            P11[u] = Pp11 - K1 * K1 * S;
            P12[u] = Pp12 - K1 * K2 * S;
            P22[u] = Pp22 - K2 * K2 * S;

            if (i >= WARM) {
                g_rec[ridx(0, k)] = make_float4(m0[u], m1[u], m2[u], mp0);
                g_rec[ridx(1, k)] = make_float4(mp1, mp2, Pp00, Pp01);
                g_rec[ridx(2, k)] = make_float4(Pp02, Pp11, Pp12, Pp22);
                g_rec[ridx(3, k)] = make_float4(P00[u], P01[u], P02[u], P11[u]);
                float* f4 = (float*)&g_rec[ridx(4, k)];
                f4[0] = P12[u]; f4[1] = P22[u];
            }
            in[u] = nin;
        }
    }
}

__global__ void __launch_bounds__(32) backward_kernel(const float* __restrict__ pmc,
                                                      float* __restrict__ out, int M) {
    int t = blockIdx.x * blockDim.x + threadIdx.x;
    if (t >= HALF) return;
    const int e[2] = { (t + 1) * CHUNK, (t + HALF + 1) * CHUNK };
    float mc = *pmc;

    float ms0[2], ms1[2], ms2[2];
    float Ps00[2], Ps01[2], Ps02[2], Ps11[2], Ps12[2], Ps22[2];
    float mpn0[2], mpn1[2], mpn2[2];
    float Ppn00[2], Ppn01[2], Ppn02[2], Ppn11[2], Ppn12[2], Ppn22[2];

#pragma unroll
    for (int u = 0; u < 2; u++) {
        int kinit = min(e[u] - 1 + WARM, TT - 1);
        float4 r0 = g_rec[ridx(0, kinit)], r1 = g_rec[ridx(1, kinit)];
        float4 r2 = g_rec[ridx(2, kinit)], r3 = g_rec[ridx(3, kinit)];
        float4 r4 = g_rec[ridx(4, kinit)];
        ms0[u] = r0.x; ms1[u] = r0.y; ms2[u] = r0.z;     // carry = filtered state
        Ps00[u] = r3.x; Ps01[u] = r3.y; Ps02[u] = r3.z;
        Ps11[u] = r3.w; Ps12[u] = r4.x; Ps22[u] = r4.y;
        mpn0[u] = r0.w; mpn1[u] = r1.x; mpn2[u] = r1.y;
        Ppn00[u] = r1.z; Ppn01[u] = r1.w; Ppn02[u] = r2.x;
        Ppn11[u] = r2.y; Ppn12[u] = r2.z; Ppn22[u] = r2.w;
        if (e[u] == TT) {  // exact top-of-sequence state; chain owning slot T-1
            int tj = g_tj[TT - 1];
            if (tj >= 0) { out[tj] = ms0[u] + mc; out[M + tj] = fmaxf(Ps00[u], 0.0f); }
        }
    }

    for (int i = 1; i < STEPS; ++i) {
#pragma unroll
        for (int u = 0; u < 2; u++) {
            int n = e[u] - 1 + WARM - i;       // slot to process (down to s = e-CHUNK)
            int nc = min(n, TT - 1);
            float4 c0 = g_rec[ridx(0, nc)], c1 = g_rec[ridx(1, nc)], c2 = g_rec[ridx(2, nc)];
            float4 c3 = g_rec[ridx(3, nc)], c4 = g_rec[ridx(4, nc)], c5 = g_rec[ridx(5, nc)];
            float4 c6 = g_rec[ridx(6, nc)];

            float mf0 = c0.x, mf1 = c0.y, mf2 = c0.z;
            float Pf00 = c3.x, Pf01 = c3.y, Pf02 = c3.z, Pf11 = c3.w, Pf12 = c4.x, Pf22 = c4.y;
            float G00 = c5.x, G01 = c5.y, G02 = c5.z, G10 = c5.w;
            float G11 = c6.x, G12 = c6.y, G20 = c6.z, G21 = c6.w, G22 = c4.z;

            bool act = (n < TT - 1);           // skip virtual steps past end

            float dm0 = ms0[u] - mpn0[u], dm1 = ms1[u] - mpn1[u], dm2 = ms2[u] - mpn2[u];
            float nm0 = mf0 + G00 * dm0 + G01 * dm1 + G02 * dm2;
            float nm1 = mf1 + G10 * dm0 + G11 * dm1 + G12 * dm2;
            float nm2 = mf2 + G20 * dm0 + G21 * dm1 + G22 * dm2;

            float D00 = Ps00[u] - Ppn00[u], D01 = Ps01[u] - Ppn01[u], D02 = Ps02[u] - Ppn02[u];
            float D11 = Ps11[u] - Ppn11[u], D12 = Ps12[u] - Ppn12[u], D22 = Ps22[u] - Ppn22[u];
            float T00 = G00 * D00 + G01 * D01 + G02 * D02;
            float T01 = G00 * D01 + G01 * D11 + G02 * D12;
            float T02 = G00 * D02 + G01 * D12 + G02 * D22;
            float T10 = G10 * D00 + G11 * D01 + G12 * D02;
            float T11 = G10 * D01 + G11 * D11 + G12 * D12;
            float T12 = G10 * D02 + G11 * D12 + G12 * D22;
            float T20 = G20 * D00 + G21 * D01 + G22 * D02;
            float T21 = G20 * D01 + G21 * D11 + G22 * D12;
            float T22 = G20 * D02 + G21 * D12 + G22 * D22;
            float nP00 = Pf00 + T00 * G00 + T01 * G01 + T02 * G02;
            float nP01 = Pf01 + T00 * G10 + T01 * G11 + T02 * G12;
            float nP02 = Pf02 + T00 * G20 + T01 * G21 + T02 * G22;
            float nP11 = Pf11 + T10 * G10 + T11 * G11 + T12 * G12;
            float nP12 = Pf12 + T10 * G20 + T11 * G21 + T12 * G22;
            float nP22 = Pf22 + T20 * G20 + T21 * G21 + T22 * G22;

            if (act) {
                ms0[u] = nm0; ms1[u] = nm1; ms2[u] = nm2;
                Ps00[u] = nP00; Ps01[u] = nP01; Ps02[u] = nP02;
                Ps11[u] = nP11; Ps12[u] = nP12; Ps22[u] = nP22;
            }

            if (n < e[u]) {  // payload slot
                int tj = g_tj[n];
                if (tj >= 0) { out[tj] = ms0[u] + mc; out[M + tj] = fmaxf(Ps00[u], 0.0f); }
            }

            // slot nc's (m_pred, P_pred) become "next" (stays at TT-1 during skips)
            mpn0[u] = c0.w; mpn1[u] = c1.x; mpn2[u] = c1.y;
            Ppn00[u] = c1.z; Ppn01[u] = c1.w; Ppn02[u] = c2.x;
            Ppn11[u] = c2.y; Ppn12[u] = c2.z; Ppn22[u] = c2.w;
        }
    }
}

extern "C" void kernel_launch(void* const* d_in, const int* in_sizes, int n_in,
                              void* d_out, int out_size) {
    const float* times = (const float*)d_in[0];
    const float* tstar = (const float*)d_in[1];
    const float* n1    = (const float*)d_in[2];
    const float* n2    = (const float*)d_in[3];
    const float* pvar  = (const float*)d_in[4];
    const float* pls   = (const float*)d_in[5];
    const float* pmc   = (const float*)d_in[6];
    int N = in_sizes[0];
    int M = in_sizes[1];
    int total = N + M;

    merge_kernel<<<(total + 255) / 256, 256>>>(times, tstar, n1, n2, pmc, N, M);
    forward_kernel<<<HALF / 32, 32>>>(pvar, pls);
    backward_kernel<<<HALF / 32, 32>>>(pmc, (float*)d_out, M);
}

// round 8
// speedup vs baseline: 4.0221x; 4.0221x over previous
#include <cuda_runtime.h>
#include <math.h>

// Problem-fixed: N_TRAIN=131072, M_TEST=65536
#define TT     196608
#define LOGC   6
#define CHUNK  64
#define NCH    (TT / CHUNK)   // 3072
#define WARM   2048

// Transposed merged inputs: index (j, chunk) -> j*NCH + chunk. (t, residual, R, is_obs)
__device__ float4 g_in_t[(size_t)CHUNK * NCH];
__device__ int    g_tj[TT];
// Filter record, SoA-transposed: field f of slot k at ((f*CHUNK + j)*NCH + c), c=k>>6, j=k&63
//  F0=(mf0,mf1,mf2,mp0)  F1=(mp1,mp2,Pp00,Pp01)  F2=(Pp02,Pp11,Pp12,Pp22)
//  F3=(Pf00,Pf01,Pf02,Pf11)  F4=(Pf12,Pf22,G22,-)  F5=(G00,G01,G02,G10)  F6=(G11,G12,G20,G21)
// F4.xy written by slot owner; F4.z (G22) written by owner of slot+1. Disjoint addresses.
__device__ float4 g_rec[(size_t)7 * CHUNK * NCH];

__device__ __forceinline__ size_t ridx(int f, int slot) {
    int c = slot >> LOGC, j = slot & (CHUNK - 1);
    return ((size_t)(f * CHUNK + j)) * NCH + c;
}

__global__ void merge_kernel(const float* __restrict__ times, const float* __restrict__ tstar,
                             const float* __restrict__ n1, const float* __restrict__ n2,
                             const float* __restrict__ pmc, int N, int M) {
    int i = blockIdx.x * blockDim.x + threadIdx.x;
    if (i < N) {
        float x = times[i];
        // stable argsort: equal keys keep train first -> position = i + #{tstar < x}
        int lo = 0, hi = M;
        while (lo < hi) { int mid = (lo + hi) >> 1; if (tstar[mid] < x) lo = mid + 1; else hi = mid; }
        int p = i + lo;
        float s2 = n2[i];
        float mc = *pmc;
        g_in_t[(size_t)(p & (CHUNK - 1)) * NCH + (p >> LOGC)] =
            make_float4(x, n1[i] / s2 - mc, 1.0f / s2, 1.0f);
        g_tj[p] = -1;
    } else if (i < N + M) {
        int j = i - N;
        float x = tstar[j];
        // position = j + #{times <= x}
        int lo = 0, hi = N;
        while (lo < hi) { int mid = (lo + hi) >> 1; if (times[mid] <= x) lo = mid + 1; else hi = mid; }
        int p = j + lo;
        g_in_t[(size_t)(p & (CHUNK - 1)) * NCH + (p >> LOGC)] = make_float4(x, 0.0f, 1.0f, 0.0f);
        g_tj[p] = j;
    }
}

// A(dt) = exp(-lam*dt) * (I + dt*Nm + 0.5 dt^2 Nm^2), Nm nilpotent
#define COMPUTE_A(dt)                                              \
    float ed = __expf(-lam * (dt));                                \
    float d2 = 0.5f * (dt) * (dt);                                 \
    float A00 = ed * (1.0f + (dt) * lam + d2 * lam2);              \
    float A01 = ed * ((dt) + d2 * (2.0f * lam));                   \
    float A02 = ed * d2;                                           \
    float A10 = ed * (-d2 * lam3);                                 \
    float A11 = ed * (1.0f + (dt) * lam - d2 * (2.0f * lam2));     \
    float A12 = ed * ((dt) - d2 * lam);                            \
    float A20 = ed * (-(dt) * lam3 + d2 * lam4);                   \
    float A21 = ed * (-3.0f * (dt) * lam2 + d2 * (2.0f * lam3));   \
    float A22 = ed * (1.0f - 2.0f * (dt) * lam + d2 * lam2);

__global__ void forward_kernel(const float* __restrict__ pvar, const float* __restrict__ pls) {
    int c = blockIdx.x * blockDim.x + threadIdx.x;
    if (c >= NCH) return;
    int s = c * CHUNK, e = s + CHUNK;
    int k0 = max(0, s - WARM);

    float var = *pvar;
    float lam = sqrtf(5.0f) / (*pls);
    float lam2 = lam * lam, lam3 = lam2 * lam, lam4 = lam2 * lam2;
    float kap = lam2 * (1.0f / 3.0f);
    float pi00 = var, pi02 = -var * kap, pi11 = var * kap, pi22 = var * lam4;

    float m0 = 0.f, m1 = 0.f, m2 = 0.f;
    float P00 = pi00, P01 = 0.f, P02 = pi02, P11 = pi11, P12 = 0.f, P22 = pi22;
    float tprev = 0.0f;
    if (k0 > 0) tprev = g_in_t[(size_t)((k0 - 1) & (CHUNK - 1)) * NCH + ((k0 - 1) >> LOGC)].x;

    float4 in = g_in_t[(size_t)(k0 & (CHUNK - 1)) * NCH + (k0 >> LOGC)];

    for (int k = k0; k < e; ++k) {
        float4 nin = in;
        if (k + 1 < e)  // prefetch next step's input
            nin = g_in_t[(size_t)((k + 1) & (CHUNK - 1)) * NCH + ((k + 1) >> LOGC)];

        float dt = (k == 0) ? 0.0f : (in.x - tprev);
        tprev = in.x;
        float r = in.y, R = in.z, obs = in.w;

        COMPUTE_A(dt);

        // Delta = P_filt(k-1) - Pinf  (Pinf has zeros at 01,12)
        float D00 = P00 - pi00, D01 = P01, D02 = P02 - pi02;
        float D11 = P11 - pi11, D12 = P12, D22 = P22 - pi22;
        // C = A * Delta
        float C00 = A00 * D00 + A01 * D01 + A02 * D02;
        float C01 = A00 * D01 + A01 * D11 + A02 * D12;
        float C02 = A00 * D02 + A01 * D12 + A02 * D22;
        float C10 = A10 * D00 + A11 * D01 + A12 * D02;
        float C11 = A10 * D01 + A11 * D11 + A12 * D12;
        float C12 = A10 * D02 + A11 * D12 + A12 * D22;
        float C20 = A20 * D00 + A21 * D01 + A22 * D02;
        float C21 = A20 * D01 + A21 * D11 + A22 * D12;
        float C22 = A20 * D02 + A21 * D12 + A22 * D22;
        // P_pred = C A^T + Pinf   (== A P A^T + Q, exact identity)
        float Pp00 = C00 * A00 + C01 * A01 + C02 * A02 + pi00;
        float Pp01 = C00 * A10 + C01 * A11 + C02 * A12;
        float Pp02 = C00 * A20 + C01 * A21 + C02 * A22 + pi02;
        float Pp11 = C10 * A10 + C11 * A11 + C12 * A12 + pi11;
        float Pp12 = C10 * A20 + C11 * A21 + C12 * A22;
        float Pp22 = C20 * A20 + C21 * A21 + C22 * A22 + pi22;

        float mp0 = A00 * m0 + A01 * m1 + A02 * m2;
        float mp1 = A10 * m0 + A11 * m1 + A12 * m2;
        float mp2 = A20 * m0 + A21 * m1 + A22 * m2;

        // Smoother gain for slot k-1: G = P_filt(k-1) A^T Ppred^{-1} = (A P_filt)^T Inv
        if (k >= s && k > 0) {
            float AP00 = C00 + A00 * pi00 + A02 * pi02;
            float AP01 = C01 + A01 * pi11;
            float AP02 = C02 + A00 * pi02 + A02 * pi22;
            float AP10 = C10 + A10 * pi00 + A12 * pi02;
            float AP11 = C11 + A11 * pi11;
            float AP12 = C12 + A10 * pi02 + A12 * pi22;
            float AP20 = C20 + A20 * pi00 + A22 * pi02;
            float AP21 = C21 + A21 * pi11;
            float AP22 = C22 + A20 * pi02 + A22 * pi22;

            float i00 = Pp11 * Pp22 - Pp12 * Pp12;
            float i01 = Pp02 * Pp12 - Pp01 * Pp22;
            float i02 = Pp01 * Pp12 - Pp02 * Pp11;
            float i11 = Pp00 * Pp22 - Pp02 * Pp02;
            float i12 = Pp01 * Pp02 - Pp00 * Pp12;
            float i22 = Pp00 * Pp11 - Pp01 * Pp01;
            float det = Pp00 * i00 + Pp01 * i01 + Pp02 * i02;
            float idet = __fdividef(1.0f, det);
            i00 *= idet; i01 *= idet; i02 *= idet; i11 *= idet; i12 *= idet; i22 *= idet;

            float G00 = AP00 * i00 + AP10 * i01 + AP20 * i02;
            float G01 = AP00 * i01 + AP10 * i11 + AP20 * i12;
            float G02 = AP00 * i02 + AP10 * i12 + AP20 * i22;
            float G10 = AP01 * i00 + AP11 * i01 + AP21 * i02;
            float G11 = AP01 * i01 + AP11 * i11 + AP21 * i12;
            float G12 = AP01 * i02 + AP11 * i12 + AP21 * i22;
            float G20 = AP02 * i00 + AP12 * i01 + AP22 * i02;
            float G21 = AP02 * i01 + AP12 * i11 + AP22 * i12;
            float G22 = AP02 * i02 + AP12 * i12 + AP22 * i22;

            int q = k - 1;
            g_rec[ridx(5, q)] = make_float4(G00, G01, G02, G10);
            g_rec[ridx(6, q)] = make_float4(G11, G12, G20, G21);
            ((float*)&g_rec[ridx(4, q)])[2] = G22;
        }

        // Measurement update
        float S = Pp00 + R;
        float iS = __fdividef(obs, S);
        float K0 = Pp00 * iS, K1 = Pp01 * iS, K2 = Pp02 * iS;
        float v = r - mp0;
        m0 = mp0 + K0 * v; m1 = mp1 + K1 * v; m2 = mp2 + K2 * v;
        P00 = Pp00 - K0 * K0 * S;
        P01 = Pp01 - K0 * K1 * S;
        P02 = Pp02 - K0 * K2 * S;
        P11 = Pp11 - K1 * K1 * S;
        P12 = Pp12 - K1 * K2 * S;
        P22 = Pp22 - K2 * K2 * S;

        if (k >= s) {
            g_rec[ridx(0, k)] = make_float4(m0, m1, m2, mp0);
            g_rec[ridx(1, k)] = make_float4(mp1, mp2, Pp00, Pp01);
            g_rec[ridx(2, k)] = make_float4(Pp02, Pp11, Pp12, Pp22);
            g_rec[ridx(3, k)] = make_float4(P00, P01, P02, P11);
            float* f4 = (float*)&g_rec[ridx(4, k)];
            f4[0] = P12; f4[1] = P22;
        }
        in = nin;
    }
}

__global__ void backward_kernel(const float* __restrict__ pmc, float* __restrict__ out, int M) {
    int c = blockIdx.x * blockDim.x + threadIdx.x;
    if (c >= NCH) return;
    int s = c * CHUNK, e = s + CHUNK;
    float mc = *pmc;

    int kinit = min(TT - 1, e - 1 + WARM);

    float ms0, ms1, ms2, Ps00, Ps01, Ps02, Ps11, Ps12, Ps22;
    float mpn0, mpn1, mpn2, Ppn00, Ppn01, Ppn02, Ppn11, Ppn12, Ppn22;
    {
        float4 r0 = g_rec[ridx(0, kinit)], r1 = g_rec[ridx(1, kinit)];
        float4 r2 = g_rec[ridx(2, kinit)], r3 = g_rec[ridx(3, kinit)];
        float4 r4 = g_rec[ridx(4, kinit)];
        ms0 = r0.x; ms1 = r0.y; ms2 = r0.z;          // init carry = filtered state
        Ps00 = r3.x; Ps01 = r3.y; Ps02 = r3.z; Ps11 = r3.w; Ps12 = r4.x; Ps22 = r4.y;
        mpn0 = r0.w; mpn1 = r1.x; mpn2 = r1.y;
        Ppn00 = r1.z; Ppn01 = r1.w; Ppn02 = r2.x; Ppn11 = r2.y; Ppn12 = r2.z; Ppn22 = r2.w;
        if (c == NCH - 1) {  // exact top-of-sequence state; only last chunk owns slot T-1
            int tj = g_tj[TT - 1];
            if (tj >= 0) { out[tj] = ms0 + mc; out[M + tj] = fmaxf(Ps00, 0.0f); }
        }
    }

    // register double-buffer prefetch
    int n0 = kinit - 1;
    float4 p0 = g_rec[ridx(0, n0)], p1 = g_rec[ridx(1, n0)], p2 = g_rec[ridx(2, n0)];
    float4 p3 = g_rec[ridx(3, n0)], p4 = g_rec[ridx(4, n0)], p5 = g_rec[ridx(5, n0)];
    float4 p6 = g_rec[ridx(6, n0)];

    for (int n = n0; n >= s; --n) {
        float4 c0 = p0, c1 = p1, c2 = p2, c3 = p3, c4 = p4, c5 = p5, c6 = p6;
        if (n > s) {
            int q = n - 1;
            p0 = g_rec[ridx(0, q)]; p1 = g_rec[ridx(1, q)]; p2 = g_rec[ridx(2, q)];
            p3 = g_rec[ridx(3, q)]; p4 = g_rec[ridx(4, q)]; p5 = g_rec[ridx(5, q)];
            p6 = g_rec[ridx(6, q)];
        }
        float mf0 = c0.x, mf1 = c0.y, mf2 = c0.z;
        float Pf00 = c3.x, Pf01 = c3.y, Pf02 = c3.z, Pf11 = c3.w, Pf12 = c4.x, Pf22 = c4.y;
        float G00 = c5.x, G01 = c5.y, G02 = c5.z, G10 = c5.w;
        float G11 = c6.x, G12 = c6.y, G20 = c6.z, G21 = c6.w, G22 = c4.z;

        // m_s = m_f + G (m_s_next - m_pred_next)
        float dm0 = ms0 - mpn0, dm1 = ms1 - mpn1, dm2 = ms2 - mpn2;
        float nm0 = mf0 + G00 * dm0 + G01 * dm1 + G02 * dm2;
        float nm1 = mf1 + G10 * dm0 + G11 * dm1 + G12 * dm2;
        float nm2 = mf2 + G20 * dm0 + G21 * dm1 + G22 * dm2;

        // P_s = P_f + G (P_s_next - P_pred_next) G^T
        float D00 = Ps00 - Ppn00, D01 = Ps01 - Ppn01, D02 = Ps02 - Ppn02;
        float D11 = Ps11 - Ppn11, D12 = Ps12 - Ppn12, D22 = Ps22 - Ppn22;
        float T00 = G00 * D00 + G01 * D01 + G02 * D02;
        float T01 = G00 * D01 + G01 * D11 + G02 * D12;
        float T02 = G00 * D02 + G01 * D12 + G02 * D22;
        float T10 = G10 * D00 + G11 * D01 + G12 * D02;
        float T11 = G10 * D01 + G11 * D11 + G12 * D12;
        float T12 = G10 * D02 + G11 * D12 + G12 * D22;
        float T20 = G20 * D00 + G21 * D01 + G22 * D02;
        float T21 = G20 * D01 + G21 * D11 + G22 * D12;
        float T22 = G20 * D02 + G21 * D12 + G22 * D22;
        Ps00 = Pf00 + T00 * G00 + T01 * G01 + T02 * G02;
        Ps01 = Pf01 + T00 * G10 + T01 * G11 + T02 * G12;
        Ps02 = Pf02 + T00 * G20 + T01 * G21 + T02 * G22;
        Ps11 = Pf11 + T10 * G10 + T11 * G11 + T12 * G12;
        Ps12 = Pf12 + T10 * G20 + T11 * G21 + T12 * G22;
        Ps22 = Pf22 + T20 * G20 + T21 * G21 + T22 * G22;
        ms0 = nm0; ms1 = nm1; ms2 = nm2;

        if (n < e) {  // payload region only
            int tj = g_tj[n];
            if (tj >= 0) { out[tj] = ms0 + mc; out[M + tj] = fmaxf(Ps00, 0.0f); }
        }

        // this slot's (m_pred, P_pred) become "next" for n-1
        mpn0 = c0.w; mpn1 = c1.x; mpn2 = c1.y;
        Ppn00 = c1.z; Ppn01 = c1.w; Ppn02 = c2.x; Ppn11 = c2.y; Ppn12 = c2.z; Ppn22 = c2.w;
    }
}

extern "C" void kernel_launch(void* const* d_in, const int* in_sizes, int n_in,
                              void* d_out, int out_size) {
    const float* times = (const float*)d_in[0];
    const float* tstar = (const float*)d_in[1];
    const float* n1    = (const float*)d_in[2];
    const float* n2    = (const float*)d_in[3];
    const float* pvar  = (const float*)d_in[4];
    const float* pls   = (const float*)d_in[5];
    const float* pmc   = (const float*)d_in[6];
    int N = in_sizes[0];
    int M = in_sizes[1];
    int total = N + M;

    merge_kernel<<<(total + 255) / 256, 256>>>(times, tstar, n1, n2, pmc, N, M);
    forward_kernel<<<(NCH + 31) / 32, 32>>>(pvar, pls);
    backward_kernel<<<(NCH + 31) / 32, 32>>>(pmc, (float*)d_out, M);
}

// round 10
// speedup vs baseline: 5.4091x; 1.3449x over previous
#include <cuda_runtime.h>
#include <math.h>

// Problem-fixed: N_TRAIN=131072, M_TEST=65536
#define TT     196608
#define LOGC   6
#define CHUNK  64
#define NCH    (TT / CHUNK)   // 3072
#define WARM   2048

// Transposed merged inputs: index (j, chunk) -> j*NCH + chunk. (t, residual, R, is_obs)
__device__ float4 g_in_t[(size_t)CHUNK * NCH];
__device__ int    g_tj[TT];
// Filter record, SoA-transposed: field f of slot k at ((f*CHUNK + j)*NCH + c), c=k>>6, j=k&63
//  F0=(mf0,mf1,mf2,mp0)  F1=(mp1,mp2,Pp00,Pp01)  F2=(Pp02,Pp11,Pp12,Pp22)
//  F3=(Pf00,Pf01,Pf02,Pf11)  F4=(Pf12,Pf22,G22,-)  F5=(G00,G01,G02,G10)  F6=(G11,G12,G20,G21)
// F4.xy written by slot owner; F4.z (G22) written by owner of slot+1. Disjoint addresses.
__device__ float4 g_rec[(size_t)7 * CHUNK * NCH];

__device__ __forceinline__ size_t ridx(int f, int slot) {
    int c = slot >> LOGC, j = slot & (CHUNK - 1);
    return ((size_t)(f * CHUNK + j)) * NCH + c;
}
__device__ __forceinline__ size_t iidx(int k) {
    return (size_t)(k & (CHUNK - 1)) * NCH + (k >> LOGC);
}

__global__ void merge_kernel(const float* __restrict__ times, const float* __restrict__ tstar,
                             const float* __restrict__ n1, const float* __restrict__ n2,
                             const float* __restrict__ pmc, int N, int M) {
    int i = blockIdx.x * blockDim.x + threadIdx.x;
    if (i < N) {
        float x = times[i];
        // stable argsort: equal keys keep train first -> position = i + #{tstar < x}
        int lo = 0, hi = M;
        while (lo < hi) { int mid = (lo + hi) >> 1; if (tstar[mid] < x) lo = mid + 1; else hi = mid; }
        int p = i + lo;
        float s2 = n2[i];
        float mc = *pmc;
        g_in_t[iidx(p)] = make_float4(x, n1[i] / s2 - mc, 1.0f / s2, 1.0f);
        g_tj[p] = -1;
    } else if (i < N + M) {
        int j = i - N;
        float x = tstar[j];
        // position = j + #{times <= x}
        int lo = 0, hi = N;
        while (lo < hi) { int mid = (lo + hi) >> 1; if (times[mid] <= x) lo = mid + 1; else hi = mid; }
        int p = j + lo;
        g_in_t[iidx(p)] = make_float4(x, 0.0f, 1.0f, 0.0f);
        g_tj[p] = j;
    }
}

// One filter step: consumes (in, tprev) -> advances (m, P); input pipeline shift.
// STORE==1: also compute+store smoother gain G (slot k-1) and the filter record (slot k).
#define FWD_STEP(STORE)                                                          \
    {                                                                            \
        float4 nin2 = g_in_t[iidx(min(k + 2, TT - 1))];                          \
        float dt = (k == 0) ? 0.0f : (in.x - tprev);                             \
        tprev = in.x;                                                            \
        float r = in.y, R = in.z, obs = in.w;                                    \
        float ed = __expf(-lam * dt);                                            \
        float d2 = 0.5f * dt * dt;                                               \
        float A00 = ed * (1.0f + dt * lam + d2 * lam2);                          \
        float A01 = ed * (dt + d2 * (2.0f * lam));                               \
        float A02 = ed * d2;                                                     \
        float A10 = ed * (-d2 * lam3);                                           \
        float A11 = ed * (1.0f + dt * lam - d2 * (2.0f * lam2));                 \
        float A12 = ed * (dt - d2 * lam);                                        \
        float A20 = ed * (-dt * lam3 + d2 * lam4);                               \
        float A21 = ed * (-3.0f * dt * lam2 + d2 * (2.0f * lam3));               \
        float A22 = ed * (1.0f - 2.0f * dt * lam + d2 * lam2);                   \
        float D00 = P00 - pi00, D01 = P01, D02 = P02 - pi02;                     \
        float D11 = P11 - pi11, D12 = P12, D22 = P22 - pi22;                     \
        float C00 = A00 * D00 + A01 * D01 + A02 * D02;                           \
        float C01 = A00 * D01 + A01 * D11 + A02 * D12;                           \
        float C02 = A00 * D02 + A01 * D12 + A02 * D22;                           \
        float C10 = A10 * D00 + A11 * D01 + A12 * D02;                           \
        float C11 = A10 * D01 + A11 * D11 + A12 * D12;                           \
        float C12 = A10 * D02 + A11 * D12 + A12 * D22;                           \
        float C20 = A20 * D00 + A21 * D01 + A22 * D02;                           \
        float C21 = A20 * D01 + A21 * D11 + A22 * D12;                           \
        float C22 = A20 * D02 + A21 * D12 + A22 * D22;                           \
        float Pp00 = C00 * A00 + C01 * A01 + C02 * A02 + pi00;                   \
        float Pp01 = C00 * A10 + C01 * A11 + C02 * A12;                          \
        float Pp02 = C00 * A20 + C01 * A21 + C02 * A22 + pi02;                   \
        float Pp11 = C10 * A10 + C11 * A11 + C12 * A12 + pi11;                   \
        float Pp12 = C10 * A20 + C11 * A21 + C12 * A22;                          \
        float Pp22 = C20 * A20 + C21 * A21 + C22 * A22 + pi22;                   \
        float mp0 = A00 * m0 + A01 * m1 + A02 * m2;                              \
        float mp1 = A10 * m0 + A11 * m1 + A12 * m2;                              \
        float mp2 = A20 * m0 + A21 * m1 + A22 * m2;                              \
        if (STORE) {                                                             \
            if (k > 0) {                                                         \
                float AP00 = C00 + A00 * pi00 + A02 * pi02;                      \
                float AP01 = C01 + A01 * pi11;                                   \
                float AP02 = C02 + A00 * pi02 + A02 * pi22;                      \
                float AP10 = C10 + A10 * pi00 + A12 * pi02;                      \
                float AP11 = C11 + A11 * pi11;                                   \
                float AP12 = C12 + A10 * pi02 + A12 * pi22;                      \
                float AP20 = C20 + A20 * pi00 + A22 * pi02;                      \
                float AP21 = C21 + A21 * pi11;                                   \
                float AP22 = C22 + A20 * pi02 + A22 * pi22;                      \
                float i00 = Pp11 * Pp22 - Pp12 * Pp12;                           \
                float i01 = Pp02 * Pp12 - Pp01 * Pp22;                           \
                float i02 = Pp01 * Pp12 - Pp02 * Pp11;                           \
                float i11 = Pp00 * Pp22 - Pp02 * Pp02;                           \
                float i12 = Pp01 * Pp02 - Pp00 * Pp12;                           \
                float i22 = Pp00 * Pp11 - Pp01 * Pp01;                           \
                float det = Pp00 * i00 + Pp01 * i01 + Pp02 * i02;                \
                float idet = __fdividef(1.0f, det);                              \
                i00 *= idet; i01 *= idet; i02 *= idet;                           \
                i11 *= idet; i12 *= idet; i22 *= idet;                           \
                float G00 = AP00 * i00 + AP10 * i01 + AP20 * i02;                \
                float G01 = AP00 * i01 + AP10 * i11 + AP20 * i12;                \
                float G02 = AP00 * i02 + AP10 * i12 + AP20 * i22;                \
                float G10 = AP01 * i00 + AP11 * i01 + AP21 * i02;                \
                float G11 = AP01 * i01 + AP11 * i11 + AP21 * i12;                \
                float G12 = AP01 * i02 + AP11 * i12 + AP21 * i22;                \
                float G20 = AP02 * i00 + AP12 * i01 + AP22 * i02;                \
                float G21 = AP02 * i01 + AP12 * i11 + AP22 * i12;                \
                float G22 = AP02 * i02 + AP12 * i12 + AP22 * i22;                \
                int q = k - 1;                                                   \
                g_rec[ridx(5, q)] = make_float4(G00, G01, G02, G10);             \
                g_rec[ridx(6, q)] = make_float4(G11, G12, G20, G21);             \
                ((float*)&g_rec[ridx(4, q)])[2] = G22;                           \
            }                                                                    \
        }                                                                        \
        float S = Pp00 + R;                                                      \
        float iS = __fdividef(obs, S);                                           \
        float K0 = Pp00 * iS, K1 = Pp01 * iS, K2 = Pp02 * iS;                    \
        float v = r - mp0;                                                       \
        m0 = mp0 + K0 * v; m1 = mp1 + K1 * v; m2 = mp2 + K2 * v;                 \
        P00 = Pp00 - K0 * K0 * S;                                                \
        P01 = Pp01 - K0 * K1 * S;                                                \
        P02 = Pp02 - K0 * K2 * S;                                                \
        P11 = Pp11 - K1 * K1 * S;                                                \
        P12 = Pp12 - K1 * K2 * S;                                                \
        P22 = Pp22 - K2 * K2 * S;                                                \
        if (STORE) {                                                             \
            g_rec[ridx(0, k)] = make_float4(m0, m1, m2, mp0);                    \
            g_rec[ridx(1, k)] = make_float4(mp1, mp2, Pp00, Pp01);               \
            g_rec[ridx(2, k)] = make_float4(Pp02, Pp11, Pp12, Pp22);             \
            g_rec[ridx(3, k)] = make_float4(P00, P01, P02, P11);                 \
            float* f4 = (float*)&g_rec[ridx(4, k)];                              \
            f4[0] = P12; f4[1] = P22;                                            \
        }                                                                        \
        in = in1; in1 = nin2;                                                    \
    }

__global__ void forward_kernel(const float* __restrict__ pvar, const float* __restrict__ pls) {
    int c = blockIdx.x * blockDim.x + threadIdx.x;
    if (c >= NCH) return;
    int s = c * CHUNK, e = s + CHUNK;
    int k0 = max(0, s - WARM);

    float var = *pvar;
    float lam = sqrtf(5.0f) / (*pls);
    float lam2 = lam * lam, lam3 = lam2 * lam, lam4 = lam2 * lam2;
    float kap = lam2 * (1.0f / 3.0f);
    float pi00 = var, pi02 = -var * kap, pi11 = var * kap, pi22 = var * lam4;

    float m0 = 0.f, m1 = 0.f, m2 = 0.f;
    float P00 = pi00, P01 = 0.f, P02 = pi02, P11 = pi11, P12 = 0.f, P22 = pi22;
    float tprev = (k0 > 0) ? g_in_t[iidx(k0 - 1)].x : 0.0f;

    // input pipeline, depth 2
    float4 in  = g_in_t[iidx(k0)];
    float4 in1 = g_in_t[iidx(min(k0 + 1, TT - 1))];

    // warm-up: branch-free body (no stores)
    for (int k = k0; k < s; ++k) FWD_STEP(0)
    // payload: stores + smoother gain
    for (int k = s; k < e; ++k) FWD_STEP(1)
}

// Backward step body; cur0..cur6 are the record fields of slot n.
#define BWD_BODY()                                                               \
        float mf0 = cur0.x, mf1 = cur0.y, mf2 = cur0.z;                          \
        float Pf00 = cur3.x, Pf01 = cur3.y, Pf02 = cur3.z;                       \
        float Pf11 = cur3.w, Pf12 = cur4.x, Pf22 = cur4.y;                       \
        float G00 = cur5.x, G01 = cur5.y, G02 = cur5.z, G10 = cur5.w;            \
        float G11 = cur6.x, G12 = cur6.y, G20 = cur6.z, G21 = cur6.w;            \
        float G22 = cur4.z;                                                      \
        float dm0 = ms0 - mpn0, dm1 = ms1 - mpn1, dm2 = ms2 - mpn2;              \
        float nm0 = mf0 + G00 * dm0 + G01 * dm1 + G02 * dm2;                     \
        float nm1 = mf1 + G10 * dm0 + G11 * dm1 + G12 * dm2;                     \
        float nm2 = mf2 + G20 * dm0 + G21 * dm1 + G22 * dm2;                     \
        float D00 = Ps00 - Ppn00, D01 = Ps01 - Ppn01, D02 = Ps02 - Ppn02;        \
        float D11 = Ps11 - Ppn11, D12 = Ps12 - Ppn12, D22 = Ps22 - Ppn22;        \
        float T00 = G00 * D00 + G01 * D01 + G02 * D02;                           \
        float T01 = G00 * D01 + G01 * D11 + G02 * D12;                           \
        float T02 = G00 * D02 + G01 * D12 + G02 * D22;                           \
        float T10 = G10 * D00 + G11 * D01 + G12 * D02;                           \
        float T11 = G10 * D01 + G11 * D11 + G12 * D12;                           \
        float T12 = G10 * D02 + G11 * D12 + G12 * D22;                           \
        float T20 = G20 * D00 + G21 * D01 + G22 * D02;                           \
        float T21 = G20 * D01 + G21 * D11 + G22 * D12;                           \
        float T22 = G20 * D02 + G21 * D12 + G22 * D22;                           \
        Ps00 = Pf00 + T00 * G00 + T01 * G01 + T02 * G02;                         \
        Ps01 = Pf01 + T00 * G10 + T01 * G11 + T02 * G12;                         \
        Ps02 = Pf02 + T00 * G20 + T01 * G21 + T02 * G22;                         \
        Ps11 = Pf11 + T10 * G10 + T11 * G11 + T12 * G12;                         \
        Ps12 = Pf12 + T10 * G20 + T11 * G21 + T12 * G22;                         \
        Ps22 = Pf22 + T20 * G20 + T21 * G21 + T22 * G22;                         \
        ms0 = nm0; ms1 = nm1; ms2 = nm2;                                         \
        mpn0 = cur0.w; mpn1 = cur1.x; mpn2 = cur1.y;                             \
        Ppn00 = cur1.z; Ppn01 = cur1.w; Ppn02 = cur2.x;                          \
        Ppn11 = cur2.y; Ppn12 = cur2.z; Ppn22 = cur2.w;

// Pipeline shift + (conditional) refill for slot n-2, then expose cur*.
#define BWD_FETCH()                                                              \
        float4 cur0 = a0, cur1 = a1, cur2 = a2, cur3 = a3,                       \
               cur4 = a4, cur5 = a5, cur6 = a6;                                  \
        a0 = b0; a1 = b1; a2 = b2; a3 = b3; a4 = b4; a5 = b5; a6 = b6;           \
        { int q = n - 2;                                                         \
          if (q >= s) {                                                          \
            b0 = g_rec[ridx(0, q)]; b1 = g_rec[ridx(1, q)];                      \
            b2 = g_rec[ridx(2, q)]; b3 = g_rec[ridx(3, q)];                      \
            b4 = g_rec[ridx(4, q)]; b5 = g_rec[ridx(5, q)];                      \
            b6 = g_rec[ridx(6, q)];                                              \
          } }

__global__ void backward_kernel(const float* __restrict__ pmc, float* __restrict__ out, int M) {
    int c = blockIdx.x * blockDim.x + threadIdx.x;
    if (c >= NCH) return;
    int s = c * CHUNK, e = s + CHUNK;
    float mc = *pmc;

    int kinit = min(TT - 1, e - 1 + WARM);

    float ms0, ms1, ms2, Ps00, Ps01, Ps02, Ps11, Ps12, Ps22;
    float mpn0, mpn1, mpn2, Ppn00, Ppn01, Ppn02, Ppn11, Ppn12, Ppn22;
    {
        float4 r0 = g_rec[ridx(0, kinit)], r1 = g_rec[ridx(1, kinit)];
        float4 r2 = g_rec[ridx(2, kinit)], r3 = g_rec[ridx(3, kinit)];
        float4 r4 = g_rec[ridx(4, kinit)];
        ms0 = r0.x; ms1 = r0.y; ms2 = r0.z;          // init carry = filtered state
        Ps00 = r3.x; Ps01 = r3.y; Ps02 = r3.z; Ps11 = r3.w; Ps12 = r4.x; Ps22 = r4.y;
        mpn0 = r0.w; mpn1 = r1.x; mpn2 = r1.y;
        Ppn00 = r1.z; Ppn01 = r1.w; Ppn02 = r2.x; Ppn11 = r2.y; Ppn12 = r2.z; Ppn22 = r2.w;
        if (c == NCH - 1) {  // exact top-of-sequence state; only last chunk owns slot T-1
            int tj = g_tj[TT - 1];
            if (tj >= 0) { out[tj] = ms0 + mc; out[M + tj] = fmaxf(Ps00, 0.0f); }
        }
    }

    // 2-deep register prefetch pipeline: a = slot n, b = slot n-1
    int n0 = kinit - 1;   // n0 >= s + 62 always (kinit >= e-1)
    float4 a0 = g_rec[ridx(0, n0)], a1 = g_rec[ridx(1, n0)], a2 = g_rec[ridx(2, n0)];
    float4 a3 = g_rec[ridx(3, n0)], a4 = g_rec[ridx(4, n0)], a5 = g_rec[ridx(5, n0)];
    float4 a6 = g_rec[ridx(6, n0)];
    int n1i = n0 - 1;
    float4 b0 = g_rec[ridx(0, n1i)], b1 = g_rec[ridx(1, n1i)], b2 = g_rec[ridx(2, n1i)];
    float4 b3 = g_rec[ridx(3, n1i)], b4 = g_rec[ridx(4, n1i)], b5 = g_rec[ridx(5, n1i)];
    float4 b6 = g_rec[ridx(6, n1i)];

    // warm phase: no output writes
    for (int n = n0; n >= e; --n) {
        BWD_FETCH()
        BWD_BODY()
    }
    // payload phase: write outputs for test slots
    for (int n = min(n0, e - 1); n >= s; --n) {
        BWD_FETCH()
        BWD_BODY()
        int tj = g_tj[n];
        if (tj >= 0) { out[tj] = ms0 + mc; out[M + tj] = fmaxf(Ps00, 0.0f); }
    }
}

extern "C" void kernel_launch(void* const* d_in, const int* in_sizes, int n_in,
                              void* d_out, int out_size) {
    const float* times = (const float*)d_in[0];
    const float* tstar = (const float*)d_in[1];
    const float* n1    = (const float*)d_in[2];
    const float* n2    = (const float*)d_in[3];
    const float* pvar  = (const float*)d_in[4];
    const float* pls   = (const float*)d_in[5];
    const float* pmc   = (const float*)d_in[6];
    int N = in_sizes[0];
    int M = in_sizes[1];
    int total = N + M;

    merge_kernel<<<(total + 255) / 256, 256>>>(times, tstar, n1, n2, pmc, N, M);
    forward_kernel<<<(NCH + 31) / 32, 32>>>(pvar, pls);
    backward_kernel<<<(NCH + 31) / 32, 32>>>(pmc, (float*)d_out, M);
}

// round 11
// speedup vs baseline: 5.7577x; 1.0644x over previous
#include <cuda_runtime.h>
#include <math.h>

// Problem-fixed: N_TRAIN=131072, M_TEST=65536
#define TT     196608
#define LOGC   6
#define CHUNK  64
#define NCH    (TT / CHUNK)   // 3072
#define WARM   2048

// Transposed merged inputs: index (j, chunk) -> j*NCH + chunk. (t, residual, R, is_obs)
__device__ float4 g_in_t[(size_t)CHUNK * NCH];
__device__ int    g_tj[TT];
// Slim smoother record, SoA-transposed: field f of slot q at ((f*CHUNK + j)*NCH + c)
//  F0=(G00,G01,G02,G10)  F1=(G11,G12,G20,G21)  F2=(G22,w0,w1,w2)  F3=(K0,K1,K2,S)
// All 4 fields of slot q are written at forward step q+1 (owner of slot q+1's chunk... i.e.
// the chunk whose payload contains step q+1), using one-step-delayed carries for w/K/S.
// Slot TT-1: F2/F3 written specially at step TT-1 (its G fields are never read).
__device__ float4 g_rec[(size_t)4 * CHUNK * NCH];
// Per-slot (m_f[0], P_f[00]) for output reconstruction, payload-read only.
__device__ float2 g_mfP[(size_t)TT];

__device__ __forceinline__ size_t ridx(int f, int slot) {
    int c = slot >> LOGC, j = slot & (CHUNK - 1);
    return ((size_t)(f * CHUNK + j)) * NCH + c;
}
__device__ __forceinline__ size_t iidx(int k) {
    return (size_t)(k & (CHUNK - 1)) * NCH + (k >> LOGC);
}

__global__ void merge_kernel(const float* __restrict__ times, const float* __restrict__ tstar,
                             const float* __restrict__ n1, const float* __restrict__ n2,
                             const float* __restrict__ pmc, int N, int M) {
    int i = blockIdx.x * blockDim.x + threadIdx.x;
    if (i < N) {
        float x = times[i];
        // stable argsort: equal keys keep train first -> position = i + #{tstar < x}
        int lo = 0, hi = M;
        while (lo < hi) { int mid = (lo + hi) >> 1; if (tstar[mid] < x) lo = mid + 1; else hi = mid; }
        int p = i + lo;
        float s2 = n2[i];
        float mc = *pmc;
        g_in_t[iidx(p)] = make_float4(x, n1[i] / s2 - mc, 1.0f / s2, 1.0f);
        g_tj[p] = -1;
    } else if (i < N + M) {
        int j = i - N;
        float x = tstar[j];
        // position = j + #{times <= x}
        int lo = 0, hi = N;
        while (lo < hi) { int mid = (lo + hi) >> 1; if (times[mid] <= x) lo = mid + 1; else hi = mid; }
        int p = j + lo;
        g_in_t[iidx(p)] = make_float4(x, 0.0f, 1.0f, 0.0f);
        g_tj[p] = j;
    }
}

// One filter step. Advances (m, P, tprev, input pipeline, w/K/S carries).
// STORE==1: compute G for slot k-1, store its 4 record fields; store g_mfP[k].
#define FWD_STEP(STORE)                                                          \
    {                                                                            \
        float4 nin2 = g_in_t[iidx(min(k + 2, TT - 1))];                          \
        float dt = (k == 0) ? 0.0f : (in.x - tprev);                             \
        tprev = in.x;                                                            \
        float r = in.y, R = in.z, obs = in.w;                                    \
        float ed = __expf(-lam * dt);                                            \
        float d2 = 0.5f * dt * dt;                                               \
        float A00 = ed * (1.0f + dt * lam + d2 * lam2);                          \
        float A01 = ed * (dt + d2 * (2.0f * lam));                               \
        float A02 = ed * d2;                                                     \
        float A10 = ed * (-d2 * lam3);                                           \
        float A11 = ed * (1.0f + dt * lam - d2 * (2.0f * lam2));                 \
        float A12 = ed * (dt - d2 * lam);                                        \
        float A20 = ed * (-dt * lam3 + d2 * lam4);                               \
        float A21 = ed * (-3.0f * dt * lam2 + d2 * (2.0f * lam3));               \
        float A22 = ed * (1.0f - 2.0f * dt * lam + d2 * lam2);                   \
        float D00 = P00 - pi00, D01 = P01, D02 = P02 - pi02;                     \
        float D11 = P11 - pi11, D12 = P12, D22 = P22 - pi22;                     \
        float C00 = A00 * D00 + A01 * D01 + A02 * D02;                           \
        float C01 = A00 * D01 + A01 * D11 + A02 * D12;                           \
        float C02 = A00 * D02 + A01 * D12 + A02 * D22;                           \
        float C10 = A10 * D00 + A11 * D01 + A12 * D02;                           \
        float C11 = A10 * D01 + A11 * D11 + A12 * D12;                           \
        float C12 = A10 * D02 + A11 * D12 + A12 * D22;                           \
        float C20 = A20 * D00 + A21 * D01 + A22 * D02;                           \
        float C21 = A20 * D01 + A21 * D11 + A22 * D12;                           \
        float C22 = A20 * D02 + A21 * D12 + A22 * D22;                           \
        float Pp00 = C00 * A00 + C01 * A01 + C02 * A02 + pi00;                   \
        float Pp01 = C00 * A10 + C01 * A11 + C02 * A12;                          \
        float Pp02 = C00 * A20 + C01 * A21 + C02 * A22 + pi02;                   \
        float Pp11 = C10 * A10 + C11 * A11 + C12 * A12 + pi11;                   \
        float Pp12 = C10 * A20 + C11 * A21 + C12 * A22;                          \
        float Pp22 = C20 * A20 + C21 * A21 + C22 * A22 + pi22;                   \
        float mp0 = A00 * m0 + A01 * m1 + A02 * m2;                              \
        float mp1 = A10 * m0 + A11 * m1 + A12 * m2;                              \
        float mp2 = A20 * m0 + A21 * m1 + A22 * m2;                              \
        if (STORE) {                                                             \
            if (k > 0) {                                                         \
                float AP00 = C00 + A00 * pi00 + A02 * pi02;                      \
                float AP01 = C01 + A01 * pi11;                                   \
                float AP02 = C02 + A00 * pi02 + A02 * pi22;                      \
                float AP10 = C10 + A10 * pi00 + A12 * pi02;                      \
                float AP11 = C11 + A11 * pi11;                                   \
                float AP12 = C12 + A10 * pi02 + A12 * pi22;                      \
                float AP20 = C20 + A20 * pi00 + A22 * pi02;                      \
                float AP21 = C21 + A21 * pi11;                                   \
                float AP22 = C22 + A20 * pi02 + A22 * pi22;                      \
                float i00 = Pp11 * Pp22 - Pp12 * Pp12;                           \
                float i01 = Pp02 * Pp12 - Pp01 * Pp22;                           \
                float i02 = Pp01 * Pp12 - Pp02 * Pp11;                           \
                float i11 = Pp00 * Pp22 - Pp02 * Pp02;                           \
                float i12 = Pp01 * Pp02 - Pp00 * Pp12;                           \
                float i22 = Pp00 * Pp11 - Pp01 * Pp01;                           \
                float det = Pp00 * i00 + Pp01 * i01 + Pp02 * i02;                \
                float idet = __fdividef(1.0f, det);                              \
                i00 *= idet; i01 *= idet; i02 *= idet;                           \
                i11 *= idet; i12 *= idet; i22 *= idet;                           \
                float G00 = AP00 * i00 + AP10 * i01 + AP20 * i02;                \
                float G01 = AP00 * i01 + AP10 * i11 + AP20 * i12;                \
                float G02 = AP00 * i02 + AP10 * i12 + AP20 * i22;                \
                float G10 = AP01 * i00 + AP11 * i01 + AP21 * i02;                \
                float G11 = AP01 * i01 + AP11 * i11 + AP21 * i12;                \
                float G12 = AP01 * i02 + AP11 * i12 + AP21 * i22;                \
                float G20 = AP02 * i00 + AP12 * i01 + AP22 * i02;                \
                float G21 = AP02 * i01 + AP12 * i11 + AP22 * i12;                \
                float G22 = AP02 * i02 + AP12 * i12 + AP22 * i22;                \
                int q = k - 1;                                                   \
                g_rec[ridx(0, q)] = make_float4(G00, G01, G02, G10);             \
                g_rec[ridx(1, q)] = make_float4(G11, G12, G20, G21);             \
                g_rec[ridx(2, q)] = make_float4(G22, pw0, pw1, pw2);             \
                g_rec[ridx(3, q)] = make_float4(pK0, pK1, pK2, pS);              \
            }                                                                    \
        }                                                                        \
        float S = Pp00 + R;                                                      \
        float iS = __fdividef(obs, S);                                           \
        float K0 = Pp00 * iS, K1 = Pp01 * iS, K2 = Pp02 * iS;                    \
        float v = r - mp0;                                                       \
        float w0 = K0 * v, w1 = K1 * v, w2 = K2 * v;                             \
        m0 = mp0 + w0; m1 = mp1 + w1; m2 = mp2 + w2;                             \
        P00 = Pp00 - K0 * K0 * S;                                                \
        P01 = Pp01 - K0 * K1 * S;                                                \
        P02 = Pp02 - K0 * K2 * S;                                                \
        P11 = Pp11 - K1 * K1 * S;                                                \
        P12 = Pp12 - K1 * K2 * S;                                                \
        P22 = Pp22 - K2 * K2 * S;                                                \
        if (STORE) {                                                             \
            g_mfP[iidx(k)] = make_float2(m0, P00);                               \
            if (k == TT - 1) {                                                   \
                g_rec[ridx(2, k)] = make_float4(0.0f, w0, w1, w2);               \
                g_rec[ridx(3, k)] = make_float4(K0, K1, K2, S);                  \
            }                                                                    \
        }                                                                        \
        pw0 = w0; pw1 = w1; pw2 = w2; pK0 = K0; pK1 = K1; pK2 = K2; pS = S;      \
        in = in1; in1 = nin2;                                                    \
    }

__global__ void forward_kernel(const float* __restrict__ pvar, const float* __restrict__ pls) {
    int c = blockIdx.x * blockDim.x + threadIdx.x;
    if (c >= NCH) return;
    int s = c * CHUNK, e = s + CHUNK;
    int k0 = max(0, s - WARM);

    float var = *pvar;
    float lam = sqrtf(5.0f) / (*pls);
    float lam2 = lam * lam, lam3 = lam2 * lam, lam4 = lam2 * lam2;
    float kap = lam2 * (1.0f / 3.0f);
    float pi00 = var, pi02 = -var * kap, pi11 = var * kap, pi22 = var * lam4;

    float m0 = 0.f, m1 = 0.f, m2 = 0.f;
    float P00 = pi00, P01 = 0.f, P02 = pi02, P11 = pi11, P12 = 0.f, P22 = pi22;
    float tprev = (k0 > 0) ? g_in_t[iidx(k0 - 1)].x : 0.0f;
    float pw0 = 0.f, pw1 = 0.f, pw2 = 0.f, pK0 = 0.f, pK1 = 0.f, pK2 = 0.f, pS = 1.f;

    // input pipeline, depth 2
    float4 in  = g_in_t[iidx(k0)];
    float4 in1 = g_in_t[iidx(min(k0 + 1, TT - 1))];

    // warm-up: branch-free body (no stores; carries w/K/S for the first payload store)
    for (int k = k0; k < s; ++k) FWD_STEP(0)
    // payload: record stores + smoother gain
    for (int k = s; k < e; ++k) FWD_STEP(1)
}

// Backward delta-form step for slot n; cur0..cur3 = record fields of slot n.
// Carries: u (m_s - m_f), E (P_s - P_f), wp/Kp/Sp = w/K/S of slot n+1.
#define BWD_BODY()                                                               \
        float G00 = cur0.x, G01 = cur0.y, G02 = cur0.z, G10 = cur0.w;            \
        float G11 = cur1.x, G12 = cur1.y, G20 = cur1.z, G21 = cur1.w;            \
        float G22 = cur2.x;                                                      \
        float t0 = u0 + wp0, t1 = u1 + wp1, t2 = u2 + wp2;                       \
        float nu0 = G00 * t0 + G01 * t1 + G02 * t2;                              \
        float nu1 = G10 * t0 + G11 * t1 + G12 * t2;                              \
        float nu2 = G20 * t0 + G21 * t1 + G22 * t2;                              \
        float q0 = Sp * Kp0, q1 = Sp * Kp1, q2 = Sp * Kp2;                       \
        float B00 = E00 - q0 * Kp0, B01 = E01 - q0 * Kp1, B02 = E02 - q0 * Kp2;  \
        float B11 = E11 - q1 * Kp1, B12 = E12 - q1 * Kp2, B22 = E22 - q2 * Kp2;  \
        float T00 = G00 * B00 + G01 * B01 + G02 * B02;                           \
        float T01 = G00 * B01 + G01 * B11 + G02 * B12;                           \
        float T02 = G00 * B02 + G01 * B12 + G02 * B22;                           \
        float T10 = G10 * B00 + G11 * B01 + G12 * B02;                           \
        float T11 = G10 * B01 + G11 * B11 + G12 * B12;                           \
        float T12 = G10 * B02 + G11 * B12 + G12 * B22;                           \
        float T20 = G20 * B00 + G21 * B01 + G22 * B02;                           \
        float T21 = G20 * B01 + G21 * B11 + G22 * B12;                           \
        float T22 = G20 * B02 + G21 * B12 + G22 * B22;                           \
        E00 = T00 * G00 + T01 * G01 + T02 * G02;                                 \
        E01 = T00 * G10 + T01 * G11 + T02 * G12;                                 \
        E02 = T00 * G20 + T01 * G21 + T02 * G22;                                 \
        E11 = T10 * G10 + T11 * G11 + T12 * G12;                                 \
        E12 = T10 * G20 + T11 * G21 + T12 * G22;                                 \
        E22 = T20 * G20 + T21 * G21 + T22 * G22;                                 \
        u0 = nu0; u1 = nu1; u2 = nu2;                                            \
        wp0 = cur2.y; wp1 = cur2.z; wp2 = cur2.w;                                \
        Kp0 = cur3.x; Kp1 = cur3.y; Kp2 = cur3.z; Sp = cur3.w;

// 2-deep pipeline shift + conditional refill of slot n-2.
#define BWD_FETCH()                                                              \
        float4 cur0 = a0, cur1 = a1, cur2 = a2, cur3 = a3;                       \
        a0 = b0; a1 = b1; a2 = b2; a3 = b3;                                      \
        { int q = n - 2;                                                         \
          if (q >= s) {                                                          \
            b0 = g_rec[ridx(0, q)]; b1 = g_rec[ridx(1, q)];                      \
            b2 = g_rec[ridx(2, q)]; b3 = g_rec[ridx(3, q)];                      \
          } }

__global__ void backward_kernel(const float* __restrict__ pmc, float* __restrict__ out, int M) {
    int c = blockIdx.x * blockDim.x + threadIdx.x;
    if (c >= NCH) return;
    int s = c * CHUNK, e = s + CHUNK;
    float mc = *pmc;

    int kinit = min(TT - 1, e - 1 + WARM);

    // delta-form carry: u = 0, E = 0 at kinit (m_s := m_f there)
    float u0 = 0.f, u1 = 0.f, u2 = 0.f;
    float E00 = 0.f, E01 = 0.f, E02 = 0.f, E11 = 0.f, E12 = 0.f, E22 = 0.f;
    float wp0, wp1, wp2, Kp0, Kp1, Kp2, Sp;
    {
        float4 f2 = g_rec[ridx(2, kinit)], f3 = g_rec[ridx(3, kinit)];
        wp0 = f2.y; wp1 = f2.z; wp2 = f2.w;
        Kp0 = f3.x; Kp1 = f3.y; Kp2 = f3.z; Sp = f3.w;
        if (c == NCH - 1) {  // only the last chunk owns slot TT-1 (exact: u=E=0)
            int tj = g_tj[TT - 1];
            if (tj >= 0) {
                float2 mf = g_mfP[iidx(TT - 1)];
                out[tj] = mf.x + mc; out[M + tj] = fmaxf(mf.y, 0.0f);
            }
        }
    }

    // 2-deep register prefetch pipeline: a = slot n, b = slot n-1
    int n0 = kinit - 1;   // n0 >= s + 62 always
    float4 a0 = g_rec[ridx(0, n0)], a1 = g_rec[ridx(1, n0)];
    float4 a2 = g_rec[ridx(2, n0)], a3 = g_rec[ridx(3, n0)];
    int n1i = n0 - 1;
    float4 b0 = g_rec[ridx(0, n1i)], b1 = g_rec[ridx(1, n1i)];
    float4 b2 = g_rec[ridx(2, n1i)], b3 = g_rec[ridx(3, n1i)];

    // warm phase: no output writes
    for (int n = n0; n >= e; --n) {
        BWD_FETCH()
        BWD_BODY()
    }
    // payload phase: reconstruct outputs at test slots
    for (int n = min(n0, e - 1); n >= s; --n) {
        BWD_FETCH()
        BWD_BODY()
        int tj = g_tj[n];
        if (tj >= 0) {
            float2 mf = g_mfP[iidx(n)];
            out[tj] = mf.x + u0 + mc;
            out[M + tj] = fmaxf(mf.y + E00, 0.0f);
        }
    }
}

extern "C" void kernel_launch(void* const* d_in, const int* in_sizes, int n_in,
                              void* d_out, int out_size) {
    const float* times = (const float*)d_in[0];
    const float* tstar = (const float*)d_in[1];
    const float* n1    = (const float*)d_in[2];
    const float* n2    = (const float*)d_in[3];
    const float* pvar  = (const float*)d_in[4];
    const float* pls   = (const float*)d_in[5];
    const float* pmc   = (const float*)d_in[6];
    int N = in_sizes[0];
    int M = in_sizes[1];
    int total = N + M;

    merge_kernel<<<(total + 255) / 256, 256>>>(times, tstar, n1, n2, pmc, N, M);
    forward_kernel<<<(NCH + 31) / 32, 32>>>(pvar, pls);
    backward_kernel<<<(NCH + 31) / 32, 32>>>(pmc, (float*)d_out, M);
}